// round 14
// baseline (speedup 1.0000x reference)
#include <cuda_runtime.h>
#include <math.h>

#define D        1024
#define PD       32
#define NPAT     256
#define TOPK     4
#define NTOK_MAX 2048
#define CAP      2048
#define TB       16            // tokens per expert tile
#define ETHREADS 512
#define RTOKS    8             // tokens per route CTA

// small routing scratch (few KB of stores total — safe)
__device__ int   g_counts[NPAT];
__device__ int   g_lists[NPAT * CAP];      // entry = tok*4 + k
__device__ float g_wts[NTOK_MAX * TOPK];   // softmax weight * scale

// dynamic smem layout for expert kernel (floats)
#define SM_XST   0                       // xs_t[1024][20] padded transpose: 20480 f
#define SM_PRAW  (1024 * 20)             // projRaw[16][32]: 512 f
#define SM_PROJT (SM_PRAW + 512)         // projT[32][16]:   512 f
#define SM_WTS   (SM_PROJT + 512)        // 16 f
#define SM_ENT   (SM_WTS + 16)           // 16 int
#define EXPERT_SMEM_BYTES ((SM_ENT + 16) * 4)

// ---------------- kernel 0: zero counts ----------------
__global__ void zero_counts_kernel() { g_counts[threadIdx.x] = 0; }

// ---------------- kernel 1: routing + out init ----------------
__global__ __launch_bounds__(256) void route_kernel(
    const float* __restrict__ x,
    const float* __restrict__ hw,     // [PD, D]
    const float* __restrict__ keys,   // [NPAT, PD]
    const float* __restrict__ scale,
    float* __restrict__ out)          // initialized to x here
{
    __shared__ float xs[RTOKS * D];
    __shared__ float h[RTOKS][PD];
    __shared__ float sims[RTOKS][NPAT];
    __shared__ float sc_s;

    const int tid  = threadIdx.x;
    const int lane = tid & 31;
    const int w    = tid >> 5;
    const int tok0 = blockIdx.x * RTOKS;

    const float4* xg4 = reinterpret_cast<const float4*>(x) + (size_t)tok0 * (D / 4);
    float4* og4 = reinterpret_cast<float4*>(out) + (size_t)tok0 * (D / 4);
    float4* xs4 = reinterpret_cast<float4*>(xs);
    #pragma unroll
    for (int i = 0; i < RTOKS; i++) {
        const float4 v = xg4[i * 256 + tid];
        xs4[i * 256 + tid] = v;
        og4[i * 256 + tid] = v;          // out = x (experts atomicAdd later)
    }
    if (tid == 0) sc_s = scale[0];
    __syncthreads();

    // hash
    {
        const float4* hw4 = reinterpret_cast<const float4*>(hw);
        #pragma unroll
        for (int jj = 0; jj < 4; jj++) {
            const int j = w * 4 + jj;
            float acc[RTOKS];
            #pragma unroll
            for (int t = 0; t < RTOKS; t++) acc[t] = 0.f;
            #pragma unroll
            for (int i = 0; i < 8; i++) {
                const float4 hv = hw4[j * (D / 4) + lane + 32 * i];
                #pragma unroll
                for (int t = 0; t < RTOKS; t++) {
                    const float4 xv = xs4[t * 256 + lane + 32 * i];
                    acc[t] += hv.x * xv.x + hv.y * xv.y + hv.z * xv.z + hv.w * xv.w;
                }
            }
            #pragma unroll
            for (int t = 0; t < RTOKS; t++) {
                float a = acc[t];
                #pragma unroll
                for (int off = 16; off; off >>= 1)
                    a += __shfl_xor_sync(0xFFFFFFFFu, a, off);
                if (lane == 0) h[t][j] = a;
            }
        }
    }
    __syncthreads();

    // sims: thread = pattern
    {
        float kreg[PD];
        const float4* k4 = reinterpret_cast<const float4*>(keys) + tid * (PD / 4);
        #pragma unroll
        for (int i = 0; i < PD / 4; i++) {
            const float4 v = k4[i];
            kreg[4 * i] = v.x; kreg[4 * i + 1] = v.y;
            kreg[4 * i + 2] = v.z; kreg[4 * i + 3] = v.w;
        }
        #pragma unroll
        for (int t = 0; t < RTOKS; t++) {
            float s = 0.f;
            #pragma unroll
            for (int i = 0; i < PD; i++) s += kreg[i] * h[t][i];
            sims[t][tid] = s;
        }
    }
    __syncthreads();

    // top-4 + softmax per token (warp w owns token w); ties -> lower index
    {
        float kval[TOPK]; int kidx[TOPK];
        for (int k = 0; k < TOPK; k++) {
            float bv = -1e30f; int bi = 0;
            #pragma unroll
            for (int t2 = 0; t2 < 8; t2++) {
                const int n = lane * 8 + t2;
                const float v = sims[w][n];
                if (v > bv) { bv = v; bi = n; }
            }
            #pragma unroll
            for (int off = 16; off; off >>= 1) {
                const float ov = __shfl_xor_sync(0xFFFFFFFFu, bv, off);
                const int   oi = __shfl_xor_sync(0xFFFFFFFFu, bi, off);
                if (ov > bv || (ov == bv && oi < bi)) { bv = ov; bi = oi; }
            }
            if (lane == 0) { kval[k] = bv; kidx[k] = bi; sims[w][bi] = -1e30f; }
            __syncwarp();
        }
        if (lane == 0) {
            const int gtok = tok0 + w;
            const float m = kval[0];
            float e[TOPK]; float ssum = 0.f;
            #pragma unroll
            for (int k = 0; k < TOPK; k++) { e[k] = expf(kval[k] - m); ssum += e[k]; }
            const float sc = sc_s / ssum;
            #pragma unroll
            for (int k = 0; k < TOPK; k++) {
                const int p = kidx[k];
                const int entry = gtok * TOPK + k;
                g_wts[entry] = e[k] * sc;
                const int slot = atomicAdd(&g_counts[p], 1);
                g_lists[p * CAP + slot] = entry;
            }
        }
    }
}

// ---------------- kernel 2: per-pattern expert ----------------
// CTA = pattern. Tiles of 16 tokens; vd/vu read from global ONCE per tile
// (16x reuse vs per-token). Output via atomicAdd into out (pre-init to x).
__global__ __launch_bounds__(ETHREADS, 1) void expert_kernel(
    const float* __restrict__ x,
    const float* __restrict__ vd,     // [NPAT, D, PD]
    const float* __restrict__ vu,     // [NPAT, PD, D]
    float* __restrict__ out)
{
    extern __shared__ float sm[];
    float* xs_t  = sm + SM_XST;    // [d][20] transposed x tile (pad vs bank conflicts)
    float* praw  = sm + SM_PRAW;   // [t][j] raw down-proj sums
    float* projT = sm + SM_PROJT;  // [j][t] silu'd, weighted
    float* wts   = sm + SM_WTS;
    int*   ents  = reinterpret_cast<int*>(sm + SM_ENT);
    __shared__ int n_s;

    const int p   = blockIdx.x;
    const int tid = threadIdx.x;
    if (tid == 0) n_s = g_counts[p];
    __syncthreads();
    const int n = n_s;
    if (n == 0) return;

    const float4* vd4 = reinterpret_cast<const float4*>(vd + (size_t)p * D * PD);
    const float4* vu4 = reinterpret_cast<const float4*>(vu + (size_t)p * PD * D);
    const float4* xg4 = reinterpret_cast<const float4*>(x);
    const float4* xst4 = reinterpret_cast<const float4*>(xs_t);
    const float4* pjT4 = reinterpret_cast<const float4*>(projT);
    float4* cbuf4 = reinterpret_cast<float4*>(xs_t);   // reused for up combine

    // down mapping: warp = ds (d-slice), lanes = (tq: 4-token group, jq: j-quad)
    const int jq = tid & 7;
    const int tq = (tid >> 3) & 3;
    const int ds = tid >> 5;           // 0..15 == warp id
    // up mapping: (col: float4 of d, jh: j-half)
    const int col = tid & 255;
    const int jh  = tid >> 8;

    for (int base = 0; base < n; base += TB) {
        const int nt = min(TB, n - base);

        if (tid < TB) {
            const int slot = (tid < nt) ? tid : 0;
            const int e = g_lists[p * CAP + base + slot];
            ents[tid] = e;
            wts[tid]  = (tid < nt) ? g_wts[e] : 0.f;
        }
        if (tid < TB * PD) praw[tid] = 0.f;
        __syncthreads();

        // ---- stage x tile transposed: xs_t[d][t], row stride 20 ----
        #pragma unroll
        for (int i = 0; i < 8; i++) {
            const int idx = tid + i * ETHREADS;     // 0..4095 float4s
            const int tt = idx >> 8, c4 = idx & 255;
            const float4 v = xg4[(size_t)(ents[tt] >> 2) * 256 + c4];
            float* dstp = xs_t + (c4 * 4) * 20 + tt;
            dstp[0]  = v.x;
            dstp[20] = v.y;
            dstp[40] = v.z;
            dstp[60] = v.w;
        }
        __syncthreads();

        // ---- down: praw[t][j] += sum_d x[t][d]*vd[d][j] ----
        // per warp-iter: ONE fully-used 128B vd line + one conflict-free LDS
        {
            float4 a0 = make_float4(0.f,0.f,0.f,0.f), a1 = a0, a2 = a0, a3 = a0;
            #pragma unroll 4
            for (int i = 0; i < 64; i++) {
                const int d = i * 16 + ds;
                const float4 xv  = xst4[d * 5 + tq];   // 4 tokens
                const float4 vdv = vd4[d * 8 + jq];    // 4 j's
                a0.x += xv.x * vdv.x; a0.y += xv.x * vdv.y; a0.z += xv.x * vdv.z; a0.w += xv.x * vdv.w;
                a1.x += xv.y * vdv.x; a1.y += xv.y * vdv.y; a1.z += xv.y * vdv.z; a1.w += xv.y * vdv.w;
                a2.x += xv.z * vdv.x; a2.y += xv.z * vdv.y; a2.z += xv.z * vdv.z; a2.w += xv.z * vdv.w;
                a3.x += xv.w * vdv.x; a3.y += xv.w * vdv.y; a3.z += xv.w * vdv.z; a3.w += xv.w * vdv.w;
            }
            // cross-warp reduce over ds via smem atomics (spread addresses)
            const int t0 = tq * 4, j0 = jq * 4;
            float* pr;
            pr = praw + (t0 + 0) * PD + j0;
            atomicAdd(pr + 0, a0.x); atomicAdd(pr + 1, a0.y); atomicAdd(pr + 2, a0.z); atomicAdd(pr + 3, a0.w);
            pr = praw + (t0 + 1) * PD + j0;
            atomicAdd(pr + 0, a1.x); atomicAdd(pr + 1, a1.y); atomicAdd(pr + 2, a1.z); atomicAdd(pr + 3, a1.w);
            pr = praw + (t0 + 2) * PD + j0;
            atomicAdd(pr + 0, a2.x); atomicAdd(pr + 1, a2.y); atomicAdd(pr + 2, a2.z); atomicAdd(pr + 3, a2.w);
            pr = praw + (t0 + 3) * PD + j0;
            atomicAdd(pr + 0, a3.x); atomicAdd(pr + 1, a3.y); atomicAdd(pr + 2, a3.z); atomicAdd(pr + 3, a3.w);
        }
        __syncthreads();

        // ---- silu * (softmax weight * scale), transpose to projT[j][t] ----
        if (tid < TB * PD) {
            const int t = tid >> 5, j = tid & 31;
            const float s = praw[tid];
            const float sig = 1.f / (1.f + expf(-s));
            projT[j * TB + t] = s * sig * wts[t];
        }
        __syncthreads();

        // ---- up: acc[t][d4] = sum_j projT[j][t] * vu[j][d4] ----
        float4 acc[TB];
        #pragma unroll
        for (int t = 0; t < TB; t++) acc[t] = make_float4(0.f,0.f,0.f,0.f);
        #pragma unroll 2
        for (int jj = 0; jj < PD / 2; jj++) {
            const int j = jh * (PD / 2) + jj;
            const float4 vv = vu4[j * 256 + col];      // 4 full lines / warp
            const float4 pA = pjT4[j * 4 + 0];
            const float4 pB = pjT4[j * 4 + 1];
            const float4 pC = pjT4[j * 4 + 2];
            const float4 pD = pjT4[j * 4 + 3];
            acc[0].x  += pA.x * vv.x; acc[0].y  += pA.x * vv.y; acc[0].z  += pA.x * vv.z; acc[0].w  += pA.x * vv.w;
            acc[1].x  += pA.y * vv.x; acc[1].y  += pA.y * vv.y; acc[1].z  += pA.y * vv.z; acc[1].w  += pA.y * vv.w;
            acc[2].x  += pA.z * vv.x; acc[2].y  += pA.z * vv.y; acc[2].z  += pA.z * vv.z; acc[2].w  += pA.z * vv.w;
            acc[3].x  += pA.w * vv.x; acc[3].y  += pA.w * vv.y; acc[3].z  += pA.w * vv.z; acc[3].w  += pA.w * vv.w;
            acc[4].x  += pB.x * vv.x; acc[4].y  += pB.x * vv.y; acc[4].z  += pB.x * vv.z; acc[4].w  += pB.x * vv.w;
            acc[5].x  += pB.y * vv.x; acc[5].y  += pB.y * vv.y; acc[5].z  += pB.y * vv.z; acc[5].w  += pB.y * vv.w;
            acc[6].x  += pB.z * vv.x; acc[6].y  += pB.z * vv.y; acc[6].z  += pB.z * vv.z; acc[6].w  += pB.z * vv.w;
            acc[7].x  += pB.w * vv.x; acc[7].y  += pB.w * vv.y; acc[7].z  += pB.w * vv.z; acc[7].w  += pB.w * vv.w;
            acc[8].x  += pC.x * vv.x; acc[8].y  += pC.x * vv.y; acc[8].z  += pC.x * vv.z; acc[8].w  += pC.x * vv.w;
            acc[9].x  += pC.y * vv.x; acc[9].y  += pC.y * vv.y; acc[9].z  += pC.y * vv.z; acc[9].w  += pC.y * vv.w;
            acc[10].x += pC.z * vv.x; acc[10].y += pC.z * vv.y; acc[10].z += pC.z * vv.z; acc[10].w += pC.z * vv.w;
            acc[11].x += pC.w * vv.x; acc[11].y += pC.w * vv.y; acc[11].z += pC.w * vv.z; acc[11].w += pC.w * vv.w;
            acc[12].x += pD.x * vv.x; acc[12].y += pD.x * vv.y; acc[12].z += pD.x * vv.z; acc[12].w += pD.x * vv.w;
            acc[13].x += pD.y * vv.x; acc[13].y += pD.y * vv.y; acc[13].z += pD.y * vv.z; acc[13].w += pD.y * vv.w;
            acc[14].x += pD.z * vv.x; acc[14].y += pD.z * vv.y; acc[14].z += pD.z * vv.z; acc[14].w += pD.z * vv.w;
            acc[15].x += pD.w * vv.x; acc[15].y += pD.w * vv.y; acc[15].z += pD.w * vv.z; acc[15].w += pD.w * vv.w;
        }
        __syncthreads();   // xs_t reads done; safe to reuse as combine buffer

        if (jh == 1) {
            #pragma unroll
            for (int t = 0; t < TB; t++) cbuf4[t * 256 + col] = acc[t];
        }
        __syncthreads();

        if (jh == 0) {
            #pragma unroll
            for (int t = 0; t < TB; t++) {
                if (t < nt) {
                    const float4 o = cbuf4[t * 256 + col];
                    float* dst = out + (size_t)(ents[t] >> 2) * D + col * 4;
                    atomicAdd(dst + 0, acc[t].x + o.x);
                    atomicAdd(dst + 1, acc[t].y + o.y);
                    atomicAdd(dst + 2, acc[t].z + o.z);
                    atomicAdd(dst + 3, acc[t].w + o.w);
                }
            }
        }
        __syncthreads();   // protect smem before next tile
    }
}

// ---------------- launcher ----------------
extern "C" void kernel_launch(void* const* d_in, const int* in_sizes, int n_in,
                              void* d_out, int out_size) {
    const float* x     = (const float*)d_in[0];
    const float* hw    = (const float*)d_in[1];
    const float* keys  = (const float*)d_in[2];
    const float* vd    = (const float*)d_in[3];
    const float* vu    = (const float*)d_in[4];
    const float* scale = (const float*)d_in[5];
    float* out = (float*)d_out;

    const int ntok = in_sizes[0] / D;   // 2048

    zero_counts_kernel<<<1, NPAT>>>();
    route_kernel<<<ntok / RTOKS, 256>>>(x, hw, keys, scale, out);
    cudaFuncSetAttribute(expert_kernel, cudaFuncAttributeMaxDynamicSharedMemorySize,
                         EXPERT_SMEM_BYTES);
    expert_kernel<<<NPAT, ETHREADS, EXPERT_SMEM_BYTES>>>(x, vd, vu, out);
}

// round 15
// speedup vs baseline: 1.4892x; 1.4892x over previous
#include <cuda_runtime.h>
#include <math.h>

#define D        1024
#define PD       32
#define NPAT     256
#define TOPK     4
#define NTOK_MAX 2048
#define CAP      2048
#define TB       16            // tokens per expert tile
#define ETHREADS 512
#define NSTRIDE  4             // tile-parallel CTAs per pattern
#define RTOKS    8             // tokens per route CTA

// small routing scratch (few KB of stores total — safe)
__device__ int   g_counts[NPAT];
__device__ int   g_lists[NPAT * CAP];      // entry = tok*4 + k
__device__ float g_wts[NTOK_MAX * TOPK];   // softmax weight * scale

// ---------------- kernel 0: zero counts ----------------
__global__ void zero_counts_kernel() { g_counts[threadIdx.x] = 0; }

// ---------------- kernel 1: routing + out init ----------------
__global__ __launch_bounds__(256) void route_kernel(
    const float* __restrict__ x,
    const float* __restrict__ hw,     // [PD, D]
    const float* __restrict__ keys,   // [NPAT, PD]
    const float* __restrict__ scale,
    float* __restrict__ out)          // initialized to x here
{
    __shared__ float xs[RTOKS * D];
    __shared__ float h[RTOKS][PD];
    __shared__ float sims[RTOKS][NPAT];
    __shared__ float sc_s;

    const int tid  = threadIdx.x;
    const int lane = tid & 31;
    const int w    = tid >> 5;
    const int tok0 = blockIdx.x * RTOKS;

    const float4* xg4 = reinterpret_cast<const float4*>(x) + (size_t)tok0 * (D / 4);
    float4* og4 = reinterpret_cast<float4*>(out) + (size_t)tok0 * (D / 4);
    float4* xs4 = reinterpret_cast<float4*>(xs);
    #pragma unroll
    for (int i = 0; i < RTOKS; i++) {
        const float4 v = xg4[i * 256 + tid];
        xs4[i * 256 + tid] = v;
        og4[i * 256 + tid] = v;          // out = x (experts red.add later)
    }
    if (tid == 0) sc_s = scale[0];
    __syncthreads();

    // hash
    {
        const float4* hw4 = reinterpret_cast<const float4*>(hw);
        #pragma unroll
        for (int jj = 0; jj < 4; jj++) {
            const int j = w * 4 + jj;
            float acc[RTOKS];
            #pragma unroll
            for (int t = 0; t < RTOKS; t++) acc[t] = 0.f;
            #pragma unroll
            for (int i = 0; i < 8; i++) {
                const float4 hv = hw4[j * (D / 4) + lane + 32 * i];
                #pragma unroll
                for (int t = 0; t < RTOKS; t++) {
                    const float4 xv = xs4[t * 256 + lane + 32 * i];
                    acc[t] += hv.x * xv.x + hv.y * xv.y + hv.z * xv.z + hv.w * xv.w;
                }
            }
            #pragma unroll
            for (int t = 0; t < RTOKS; t++) {
                float a = acc[t];
                #pragma unroll
                for (int off = 16; off; off >>= 1)
                    a += __shfl_xor_sync(0xFFFFFFFFu, a, off);
                if (lane == 0) h[t][j] = a;
            }
        }
    }
    __syncthreads();

    // sims: thread = pattern
    {
        float kreg[PD];
        const float4* k4 = reinterpret_cast<const float4*>(keys) + tid * (PD / 4);
        #pragma unroll
        for (int i = 0; i < PD / 4; i++) {
            const float4 v = k4[i];
            kreg[4 * i] = v.x; kreg[4 * i + 1] = v.y;
            kreg[4 * i + 2] = v.z; kreg[4 * i + 3] = v.w;
        }
        #pragma unroll
        for (int t = 0; t < RTOKS; t++) {
            float s = 0.f;
            #pragma unroll
            for (int i = 0; i < PD; i++) s += kreg[i] * h[t][i];
            sims[t][tid] = s;
        }
    }
    __syncthreads();

    // top-4 + softmax per token (warp w owns token w); ties -> lower index
    {
        float kval[TOPK]; int kidx[TOPK];
        for (int k = 0; k < TOPK; k++) {
            float bv = -1e30f; int bi = 0;
            #pragma unroll
            for (int t2 = 0; t2 < 8; t2++) {
                const int n = lane * 8 + t2;
                const float v = sims[w][n];
                if (v > bv) { bv = v; bi = n; }
            }
            #pragma unroll
            for (int off = 16; off; off >>= 1) {
                const float ov = __shfl_xor_sync(0xFFFFFFFFu, bv, off);
                const int   oi = __shfl_xor_sync(0xFFFFFFFFu, bi, off);
                if (ov > bv || (ov == bv && oi < bi)) { bv = ov; bi = oi; }
            }
            if (lane == 0) { kval[k] = bv; kidx[k] = bi; sims[w][bi] = -1e30f; }
            __syncwarp();
        }
        if (lane == 0) {
            const int gtok = tok0 + w;
            const float m = kval[0];
            float e[TOPK]; float ssum = 0.f;
            #pragma unroll
            for (int k = 0; k < TOPK; k++) { e[k] = expf(kval[k] - m); ssum += e[k]; }
            const float sc = sc_s / ssum;
            #pragma unroll
            for (int k = 0; k < TOPK; k++) {
                const int p = kidx[k];
                const int entry = gtok * TOPK + k;
                g_wts[entry] = e[k] * sc;
                const int slot = atomicAdd(&g_counts[p], 1);
                g_lists[p * CAP + slot] = entry;
            }
        }
    }
}

// ---------------- kernel 2: per-pattern expert ----------------
// grid (NPAT, NSTRIDE); CTA (p, y) handles tiles y, y+4, ... of pattern p.
// Down: warp = token; lane = (ks: 4 K-slices, jq: 8 j-quads); shuffle reduce.
// Up:   thread = (col: float4 of d, th: token half); red.global.add.v4 out.
__global__ __launch_bounds__(ETHREADS, 2) void expert_kernel(
    const float* __restrict__ x,
    const float* __restrict__ vd,     // [NPAT, D, PD]
    const float* __restrict__ vu,     // [NPAT, PD, D]
    float* __restrict__ out)
{
    __shared__ float praw[TB * PD];    // [t][j]
    __shared__ float projT[PD * TB];   // [j][t]
    __shared__ float wts[TB];
    __shared__ int   ents[TB];
    __shared__ int   n_s;

    const int p   = blockIdx.x;
    const int tid = threadIdx.x;
    if (tid == 0) n_s = g_counts[p];
    __syncthreads();
    const int n = n_s;
    if ((int)blockIdx.y * TB >= n) return;

    const float4* vd4 = reinterpret_cast<const float4*>(vd + (size_t)p * D * PD);
    const float4* vu4 = reinterpret_cast<const float4*>(vu + (size_t)p * PD * D);
    const float4* xg4 = reinterpret_cast<const float4*>(x);
    const float4* pjT4 = reinterpret_cast<const float4*>(projT);
    float4* praw4 = reinterpret_cast<float4*>(praw);

    const int lane = tid & 31;
    const int w    = tid >> 5;         // down: warp = token slot (0..15)
    const int jq   = lane & 7;         // j-quad
    const int ks   = lane >> 3;        // K-slice (256 d each)
    const int col  = tid & 255;        // up: float4 of d
    const int th   = tid >> 8;         // up: token half

    for (int base = blockIdx.y * TB; base < n; base += NSTRIDE * TB) {
        const int nt = min(TB, n - base);

        if (tid < TB) {
            const int slot = (tid < nt) ? tid : 0;
            const int e = g_lists[p * CAP + base + slot];
            ents[tid] = e;
            wts[tid]  = (tid < nt) ? g_wts[e] : 0.f;
        }
        __syncthreads();

        // ---- down: praw[t][j] = sum_d x[t][d] * vd[d][j] ----
        {
            const int myTok = ents[w] >> 2;
            const float4* xrow = xg4 + (size_t)myTok * 256 + ks * 64;
            float4 acc = make_float4(0.f, 0.f, 0.f, 0.f);
            #pragma unroll 4
            for (int i = 0; i < 64; i++) {
                const float4 xv = xrow[i];                 // 4 d's
                const int d0 = ks * 256 + i * 4;
                const float4 v0 = vd4[(d0 + 0) * 8 + jq];  // 4 full lines/warp-instr
                const float4 v1 = vd4[(d0 + 1) * 8 + jq];
                const float4 v2 = vd4[(d0 + 2) * 8 + jq];
                const float4 v3 = vd4[(d0 + 3) * 8 + jq];
                acc.x += xv.x * v0.x + xv.y * v1.x + xv.z * v2.x + xv.w * v3.x;
                acc.y += xv.x * v0.y + xv.y * v1.y + xv.z * v2.y + xv.w * v3.y;
                acc.z += xv.x * v0.z + xv.y * v1.z + xv.z * v2.z + xv.w * v3.z;
                acc.w += xv.x * v0.w + xv.y * v1.w + xv.z * v2.w + xv.w * v3.w;
            }
            // reduce over ks (lane bits 3,4) — no atomics
            #pragma unroll
            for (int off = 8; off < 32; off <<= 1) {
                acc.x += __shfl_xor_sync(0xFFFFFFFFu, acc.x, off);
                acc.y += __shfl_xor_sync(0xFFFFFFFFu, acc.y, off);
                acc.z += __shfl_xor_sync(0xFFFFFFFFu, acc.z, off);
                acc.w += __shfl_xor_sync(0xFFFFFFFFu, acc.w, off);
            }
            if (ks == 0) praw4[w * 8 + jq] = acc;
        }
        __syncthreads();

        // ---- silu * weight, transpose to projT[j][t] ----
        {
            const int t = tid >> 5, j = tid & 31;     // 512 = TB*PD exactly
            const float s = praw[t * PD + j];
            const float sig = 1.f / (1.f + expf(-s));
            projT[j * TB + t] = s * sig * wts[t];
        }
        __syncthreads();

        // ---- up: out[t][d] += sum_j projT[j][t] * vu[j][d] ----
        {
            float4 acc[8];
            #pragma unroll
            for (int t = 0; t < 8; t++) acc[t] = make_float4(0.f, 0.f, 0.f, 0.f);
            #pragma unroll 4
            for (int j = 0; j < PD; j++) {
                const float4 vv = vu4[j * 256 + col];      // 4 full lines/warp
                const float4 pA = pjT4[j * 4 + th * 2 + 0];
                const float4 pB = pjT4[j * 4 + th * 2 + 1];
                acc[0].x += pA.x * vv.x; acc[0].y += pA.x * vv.y; acc[0].z += pA.x * vv.z; acc[0].w += pA.x * vv.w;
                acc[1].x += pA.y * vv.x; acc[1].y += pA.y * vv.y; acc[1].z += pA.y * vv.z; acc[1].w += pA.y * vv.w;
                acc[2].x += pA.z * vv.x; acc[2].y += pA.z * vv.y; acc[2].z += pA.z * vv.z; acc[2].w += pA.z * vv.w;
                acc[3].x += pA.w * vv.x; acc[3].y += pA.w * vv.y; acc[3].z += pA.w * vv.z; acc[3].w += pA.w * vv.w;
                acc[4].x += pB.x * vv.x; acc[4].y += pB.x * vv.y; acc[4].z += pB.x * vv.z; acc[4].w += pB.x * vv.w;
                acc[5].x += pB.y * vv.x; acc[5].y += pB.y * vv.y; acc[5].z += pB.y * vv.z; acc[5].w += pB.y * vv.w;
                acc[6].x += pB.z * vv.x; acc[6].y += pB.z * vv.y; acc[6].z += pB.z * vv.z; acc[6].w += pB.z * vv.w;
                acc[7].x += pB.w * vv.x; acc[7].y += pB.w * vv.y; acc[7].z += pB.w * vv.z; acc[7].w += pB.w * vv.w;
            }
            #pragma unroll
            for (int t = 0; t < 8; t++) {
                const int slot = th * 8 + t;
                if (slot < nt) {
                    float* dst = out + (size_t)(ents[slot] >> 2) * D + col * 4;
                    asm volatile("red.global.add.v4.f32 [%0], {%1, %2, %3, %4};"
                                 :: "l"(dst), "f"(acc[t].x), "f"(acc[t].y),
                                    "f"(acc[t].z), "f"(acc[t].w) : "memory");
                }
            }
        }
        __syncthreads();   // protect smem before next tile
    }
}

// ---------------- launcher ----------------
extern "C" void kernel_launch(void* const* d_in, const int* in_sizes, int n_in,
                              void* d_out, int out_size) {
    const float* x     = (const float*)d_in[0];
    const float* hw    = (const float*)d_in[1];
    const float* keys  = (const float*)d_in[2];
    const float* vd    = (const float*)d_in[3];
    const float* vu    = (const float*)d_in[4];
    const float* scale = (const float*)d_in[5];
    float* out = (float*)d_out;

    const int ntok = in_sizes[0] / D;   // 2048

    zero_counts_kernel<<<1, NPAT>>>();
    route_kernel<<<ntok / RTOKS, 256>>>(x, hw, keys, scale, out);
    expert_kernel<<<dim3(NPAT, NSTRIDE), ETHREADS>>>(x, vd, vu, out);
}